// round 12
// baseline (speedup 1.0000x reference)
#include <cuda_runtime.h>
#include <cuda_bf16.h>
#include <stdint.h>
#include <math.h>

// CommNetWork fused, split-bf16 mma.sync (m16n8k16, fp32 acc), 1024 threads/CTA.
// B=256, N=64 agents, D_IN=128, H0=256, H1=256, H2=64. One CTA per batch.
// Precision: x*w ~= xh*wh + xh*wl + xl*wh (hi/lo bf16 split, fp32 accumulate).
// Comm factorization: c=(S-h)/64; W_ih pre-scaled by -1/64 so gi and gh share
// one accumulator; S-term t[col] accumulated from staged chunks.
// 32 warps (8/SMSP) in a 2(M)x16(N) grid: each warp 32 rows x 16 cols (MT=2,NT=2)
// to limit A-fragment crossbar duplication while maximizing latency hiding.

#define ROWS    64
#define NTHREADS 1024
#define LDA_ACT 264   // bf16 elems per activation row (256+8 pad)
#define LDW     40    // bf16 elems per weight-chunk row (32+8 pad)
#define KCH     32    // k per staged chunk (double buffered)

#define OFF_ENC 0
#define OFF_OBS 32768
#define OFF_IH  98304
#define OFF_HH  294912
#define OFF_VAL 491520
#define OFF_DEC 557056
#define W_TOTAL 573440

__device__ __align__(16) __nv_bfloat16 g_whi[W_TOTAL];
__device__ __align__(16) __nv_bfloat16 g_wlo[W_TOTAL];

struct Smem {
    __nv_bfloat16 a1h[ROWS * LDA_ACT];
    __nv_bfloat16 a1l[ROWS * LDA_ACT];
    __nv_bfloat16 a2h[ROWS * LDA_ACT];
    __nv_bfloat16 a2l[ROWS * LDA_ACT];
    __nv_bfloat16 wh[2][256 * LDW];
    __nv_bfloat16 wl[2][256 * LDW];
    float S[256];
    float t[256];
};  // 219136 bytes

// ------------------------- weight conversion pre-pass -------------------
__global__ void conv_weights(const float* __restrict__ enc, const float* __restrict__ obsw,
                             const float* __restrict__ ih,  const float* __restrict__ hh,
                             const float* __restrict__ val, const float* __restrict__ dec)
{
    int i = blockIdx.x * blockDim.x + threadIdx.x;
    if (i >= W_TOTAL) return;
    const float* src;
    int off;
    float scale = 1.0f;
    if (i < OFF_OBS)      { src = enc;  off = i; }
    else if (i < OFF_IH)  { src = obsw; off = i - OFF_OBS; }
    else if (i < OFF_HH)  { src = ih;   off = i - OFF_IH; scale = -0.015625f; }
    else if (i < OFF_VAL) { src = hh;   off = i - OFF_HH; }
    else if (i < OFF_DEC) { src = val;  off = i - OFF_VAL; }
    else                  { src = dec;  off = i - OFF_DEC; }
    float v = src[off] * scale;
    __nv_bfloat16 h = __float2bfloat16(v);
    g_whi[i] = h;
    g_wlo[i] = __float2bfloat16(v - __bfloat162float(h));
}

// ------------------------- device helpers --------------------------------
__device__ __forceinline__ float sigm(float x) { return 1.0f / (1.0f + __expf(-x)); }

__device__ __forceinline__ void cp16(void* dst, const void* src) {
    uint32_t d = (uint32_t)__cvta_generic_to_shared(dst);
    asm volatile("cp.async.cg.shared.global [%0], [%1], 16;\n" :: "r"(d), "l"(src));
}
__device__ __forceinline__ void cp_commit() { asm volatile("cp.async.commit_group;\n" ::); }
__device__ __forceinline__ void cp_wait1()  { asm volatile("cp.async.wait_group 1;\n" ::); }
__device__ __forceinline__ void cp_wait0()  { asm volatile("cp.async.wait_group 0;\n" ::); }

__device__ __forceinline__ void mma_bf16(float* d,
                                         uint32_t a0, uint32_t a1, uint32_t a2, uint32_t a3,
                                         uint32_t b0, uint32_t b1)
{
    asm volatile("mma.sync.aligned.m16n8k16.row.col.f32.bf16.bf16.f32 "
                 "{%0,%1,%2,%3}, {%4,%5,%6,%7}, {%8,%9}, {%0,%1,%2,%3};\n"
                 : "+f"(d[0]), "+f"(d[1]), "+f"(d[2]), "+f"(d[3])
                 : "r"(a0), "r"(a1), "r"(a2), "r"(a3), "r"(b0), "r"(b1));
}

__device__ __forceinline__ void stage(Smem& s, int buf,
                                      const __nv_bfloat16* __restrict__ ghi,
                                      const __nv_bfloat16* __restrict__ glo,
                                      int col0, int Ksrc, int k0, int nrows, int tid)
{
    int total = nrows * 4;
    for (int idx = tid; idx < total; idx += NTHREADS) {
        int r = idx >> 2;
        int seg = idx & 3;
        size_t so = (size_t)(col0 + r) * Ksrc + k0 + seg * 8;
        cp16(&s.wh[buf][r * LDW + seg * 8], ghi + so);
        cp16(&s.wl[buf][r * LDW + seg * 8], glo + so);
    }
    cp_commit();
}

// one 32-k chunk: acc += Ahi*Whi + Ahi*Wlo + Alo*Whi
// Warp owns MT m16-tiles starting at tile m0, NT n8-tiles starting at col n0.
template<int NT, int MT>
__device__ __forceinline__ void mma_chunk(const __nv_bfloat16* __restrict__ ah,
                                          const __nv_bfloat16* __restrict__ al,
                                          const __nv_bfloat16* __restrict__ wh,
                                          const __nv_bfloat16* __restrict__ wl,
                                          int kbase, int m0, int n0, int g, int t4, float* acc)
{
#pragma unroll
    for (int ks = 0; ks < 2; ++ks) {
        int klA = kbase + ks * 16 + 2 * t4;
        int klW = ks * 16 + 2 * t4;
        uint32_t bh0[NT], bh1[NT], bl0[NT], bl1[NT];
#pragma unroll
        for (int nt = 0; nt < NT; ++nt) {
            int wrow = (n0 + nt * 8 + g) * LDW + klW;
            bh0[nt] = *(const uint32_t*)&wh[wrow];
            bh1[nt] = *(const uint32_t*)&wh[wrow + 8];
            bl0[nt] = *(const uint32_t*)&wl[wrow];
            bl1[nt] = *(const uint32_t*)&wl[wrow + 8];
        }
#pragma unroll
        for (int mt = 0; mt < MT; ++mt) {
            int ab = ((m0 + mt) * 16 + g) * LDA_ACT + klA;
            uint32_t A0 = *(const uint32_t*)&ah[ab];
            uint32_t A1 = *(const uint32_t*)&ah[ab + 8 * LDA_ACT];
            uint32_t A2 = *(const uint32_t*)&ah[ab + 8];
            uint32_t A3 = *(const uint32_t*)&ah[ab + 8 * LDA_ACT + 8];
            uint32_t L0 = *(const uint32_t*)&al[ab];
            uint32_t L1 = *(const uint32_t*)&al[ab + 8 * LDA_ACT];
            uint32_t L2 = *(const uint32_t*)&al[ab + 8];
            uint32_t L3 = *(const uint32_t*)&al[ab + 8 * LDA_ACT + 8];
#pragma unroll
            for (int nt = 0; nt < NT; ++nt) {
                float* d = acc + (mt * NT + nt) * 4;
                mma_bf16(d, A0, A1, A2, A3, bh0[nt], bh1[nt]);
                mma_bf16(d, A0, A1, A2, A3, bl0[nt], bl1[nt]);
                mma_bf16(d, L0, L1, L2, L3, bh0[nt], bh1[nt]);
            }
        }
    }
}

// NACT: number of warps that run MMAs (all warps stage + sync).
template<int NT, int MT, bool TACC, int NACT>
__device__ __forceinline__ void gemm_pass(Smem& s,
                                          const __nv_bfloat16* __restrict__ ah,
                                          const __nv_bfloat16* __restrict__ al,
                                          const __nv_bfloat16* __restrict__ ghi,
                                          const __nv_bfloat16* __restrict__ glo,
                                          int col0, int Ksrc, int Kdim, int nrows,
                                          int m0, int n0, int g, int t4, int tid, int wid,
                                          float* acc)
{
    const int nch = Kdim / KCH;
    stage(s, 0, ghi, glo, col0, Ksrc, 0, nrows, tid);
    for (int c = 0; c < nch; ++c) {
        int cur = c & 1;
        bool more = (c + 1 < nch);
        if (more) {
            stage(s, 1 - cur, ghi, glo, col0, Ksrc, (c + 1) * KCH, nrows, tid);
            cp_wait1();
        } else {
            cp_wait0();
        }
        __syncthreads();
        if (TACC && tid < 256) {
            float sum = 0.0f;
            const __nv_bfloat16* w1 = &s.wh[cur][tid * LDW];
            const __nv_bfloat16* w2 = &s.wl[cur][tid * LDW];
#pragma unroll
            for (int kk = 0; kk < KCH; ++kk) {
                sum += s.S[c * KCH + kk] *
                       (__bfloat162float(w1[kk]) + __bfloat162float(w2[kk]));
            }
            s.t[tid] += sum;
        }
        if (wid < NACT) {
            mma_chunk<NT, MT>(ah, al, s.wh[cur], s.wl[cur], c * KCH, m0, n0, g, t4, acc);
        }
        __syncthreads();
    }
}

__device__ __forceinline__ void store_pair(__nv_bfloat16* hi, __nv_bfloat16* lo,
                                           int row, int col, float v0, float v1)
{
    __nv_bfloat16 h0 = __float2bfloat16(v0);
    __nv_bfloat16 h1 = __float2bfloat16(v1);
    __nv_bfloat162 hp;
    hp.x = h0;
    hp.y = h1;
    __nv_bfloat162 lp;
    lp.x = __float2bfloat16(v0 - __bfloat162float(h0));
    lp.y = __float2bfloat16(v1 - __bfloat162float(h1));
    *reinterpret_cast<__nv_bfloat162*>(&hi[row * LDA_ACT + col]) = hp;
    *reinterpret_cast<__nv_bfloat162*>(&lo[row * LDA_ACT + col]) = lp;
}

__device__ __forceinline__ float2 load_pair(const __nv_bfloat16* hi, const __nv_bfloat16* lo,
                                            int row, int col)
{
    __nv_bfloat162 hp = *reinterpret_cast<const __nv_bfloat162*>(&hi[row * LDA_ACT + col]);
    __nv_bfloat162 lp = *reinterpret_cast<const __nv_bfloat162*>(&lo[row * LDA_ACT + col]);
    float2 r;
    r.x = __bfloat162float(hp.x) + __bfloat162float(lp.x);
    r.y = __bfloat162float(hp.y) + __bfloat162float(lp.y);
    return r;
}

__device__ __forceinline__ void zero16(float* a)
{
#pragma unroll
    for (int i = 0; i < 16; ++i) { a[i] = 0.0f; }
}

// ------------------------- main fused kernel -----------------------------
__global__ void __launch_bounds__(NTHREADS, 1)
commnet_mma_kernel(const float* __restrict__ obs,
                   const float* __restrict__ b_enc, const float* __restrict__ b_obs,
                   const float* __restrict__ b_ih,  const float* __restrict__ b_hh,
                   const float* __restrict__ b_val, const float* __restrict__ b_dec,
                   float* __restrict__ out)
{
    extern __shared__ char smem_raw[];
    Smem& s = *reinterpret_cast<Smem*>(smem_raw);

    const int tid  = threadIdx.x;
    const int bid  = blockIdx.x;
    const int wid  = tid >> 5;
    const int lane = tid & 31;
    const int g    = lane >> 2;
    const int t4   = lane & 3;
    const int mg   = wid & 1;        // m-group: rows mg*32 .. mg*32+31
    const int ng   = wid >> 1;       // n-group: cols ng*16 .. ng*16+15
    const int m0g  = mg * 2;         // first m16-tile index
    const int n0g  = ng * 16;        // col base

    float acc[16];

    // ---- P1: load obs [64 x 128] -> a1 hi/lo ----
    {
        const float* ob = obs + (size_t)bid * ROWS * 128;
        for (int idx = tid; idx < ROWS * 128; idx += NTHREADS) {
            int r = idx >> 7;
            int k = idx & 127;
            float v = ob[idx];
            __nv_bfloat16 h = __float2bfloat16(v);
            s.a1h[r * LDA_ACT + k] = h;
            s.a1l[r * LDA_ACT + k] = __float2bfloat16(v - __bfloat162float(h));
        }
    }
    __syncthreads();

    // ---- P2: x = relu(obs @ W_enc^T + b_enc) -> a2 ----
    zero16(acc);
    gemm_pass<2, 2, false, 32>(s, s.a1h, s.a1l, g_whi + OFF_ENC, g_wlo + OFF_ENC,
                               0, 128, 128, 256, m0g, n0g, g, t4, tid, wid, acc);
    for (int mt = 0; mt < 2; ++mt) {
        for (int nt = 0; nt < 2; ++nt) {
            int col = n0g + nt * 8 + 2 * t4;
            int r0 = (m0g + mt) * 16 + g;
            const float* d = acc + (mt * 2 + nt) * 4;
            float b0 = __ldg(&b_enc[col]);
            float b1 = __ldg(&b_enc[col + 1]);
            store_pair(s.a2h, s.a2l, r0, col, fmaxf(d[0] + b0, 0.0f), fmaxf(d[1] + b1, 0.0f));
            store_pair(s.a2h, s.a2l, r0 + 8, col, fmaxf(d[2] + b0, 0.0f), fmaxf(d[3] + b1, 0.0f));
        }
    }

    // ---- P3: h = x @ W_obs^T + b_obs -> a1 ----
    zero16(acc);
    gemm_pass<2, 2, false, 32>(s, s.a2h, s.a2l, g_whi + OFF_OBS, g_wlo + OFF_OBS,
                               0, 256, 256, 256, m0g, n0g, g, t4, tid, wid, acc);
    for (int mt = 0; mt < 2; ++mt) {
        for (int nt = 0; nt < 2; ++nt) {
            int col = n0g + nt * 8 + 2 * t4;
            int r0 = (m0g + mt) * 16 + g;
            const float* d = acc + (mt * 2 + nt) * 4;
            float b0 = __ldg(&b_obs[col]);
            float b1 = __ldg(&b_obs[col + 1]);
            store_pair(s.a1h, s.a1l, r0, col, d[0] + b0, d[1] + b1);
            store_pair(s.a1h, s.a1l, r0 + 8, col, d[2] + b0, d[3] + b1);
        }
    }
    __syncthreads();

    // ---- P4: S = column sums of h ----
    if (tid < 256) {
        float sum = 0.0f;
#pragma unroll 8
        for (int r = 0; r < ROWS; ++r) {
            sum += __bfloat162float(s.a1h[r * LDA_ACT + tid]) +
                   __bfloat162float(s.a1l[r * LDA_ACT + tid]);
        }
        s.S[tid] = sum;
        s.t[tid] = 0.0f;
    }
    __syncthreads();

    // ======== P5 GRU (r, n, z; fragments round-trip through a2) ========

    // r gate
    zero16(acc);
    gemm_pass<2, 2, false, 32>(s, s.a1h, s.a1l, g_whi + OFF_HH, g_wlo + OFF_HH,
                               0, 256, 256, 256, m0g, n0g, g, t4, tid, wid, acc);
    gemm_pass<2, 2, true, 32>(s, s.a1h, s.a1l, g_whi + OFF_IH, g_wlo + OFF_IH,
                              0, 256, 256, 256, m0g, n0g, g, t4, tid, wid, acc);
    for (int mt = 0; mt < 2; ++mt) {
        for (int nt = 0; nt < 2; ++nt) {
            int col = n0g + nt * 8 + 2 * t4;
            int r0 = (m0g + mt) * 16 + g;
            float* d = acc + (mt * 2 + nt) * 4;
            float c0 = -s.t[col] + __ldg(&b_ih[col]) + __ldg(&b_hh[col]);
            float c1 = -s.t[col + 1] + __ldg(&b_ih[col + 1]) + __ldg(&b_hh[col + 1]);
            store_pair(s.a2h, s.a2l, r0, col, sigm(d[0] + c0), sigm(d[1] + c1));
            store_pair(s.a2h, s.a2l, r0 + 8, col, sigm(d[2] + c0), sigm(d[3] + c1));
        }
    }
    __syncthreads();
    if (tid < 256) { s.t[tid] = 0.0f; }

    // n gate
    zero16(acc);
    gemm_pass<2, 2, false, 32>(s, s.a1h, s.a1l, g_whi + OFF_HH, g_wlo + OFF_HH,
                               512, 256, 256, 256, m0g, n0g, g, t4, tid, wid, acc);
    for (int mt = 0; mt < 2; ++mt) {
        for (int nt = 0; nt < 2; ++nt) {
            int col = n0g + nt * 8 + 2 * t4;
            int r0 = (m0g + mt) * 16 + g;
            float* d = acc + (mt * 2 + nt) * 4;
            float b0 = __ldg(&b_hh[512 + col]);
            float b1 = __ldg(&b_hh[512 + col + 1]);
            float2 ra = load_pair(s.a2h, s.a2l, r0, col);
            float2 rb = load_pair(s.a2h, s.a2l, r0 + 8, col);
            d[0] = ra.x * (d[0] + b0);
            d[1] = ra.y * (d[1] + b1);
            d[2] = rb.x * (d[2] + b0);
            d[3] = rb.y * (d[3] + b1);
        }
    }
    gemm_pass<2, 2, true, 32>(s, s.a1h, s.a1l, g_whi + OFF_IH, g_wlo + OFF_IH,
                              512, 256, 256, 256, m0g, n0g, g, t4, tid, wid, acc);
    for (int mt = 0; mt < 2; ++mt) {
        for (int nt = 0; nt < 2; ++nt) {
            int col = n0g + nt * 8 + 2 * t4;
            int r0 = (m0g + mt) * 16 + g;
            float* d = acc + (mt * 2 + nt) * 4;
            float c0 = -s.t[col] + __ldg(&b_ih[512 + col]);
            float c1 = -s.t[col + 1] + __ldg(&b_ih[512 + col + 1]);
            store_pair(s.a2h, s.a2l, r0, col, tanhf(d[0] + c0), tanhf(d[1] + c1));
            store_pair(s.a2h, s.a2l, r0 + 8, col, tanhf(d[2] + c0), tanhf(d[3] + c1));
        }
    }
    __syncthreads();
    if (tid < 256) { s.t[tid] = 0.0f; }

    // z gate + blend
    zero16(acc);
    gemm_pass<2, 2, false, 32>(s, s.a1h, s.a1l, g_whi + OFF_HH, g_wlo + OFF_HH,
                               256, 256, 256, 256, m0g, n0g, g, t4, tid, wid, acc);
    gemm_pass<2, 2, true, 32>(s, s.a1h, s.a1l, g_whi + OFF_IH, g_wlo + OFF_IH,
                              256, 256, 256, 256, m0g, n0g, g, t4, tid, wid, acc);
    for (int mt = 0; mt < 2; ++mt) {
        for (int nt = 0; nt < 2; ++nt) {
            int col = n0g + nt * 8 + 2 * t4;
            int r0 = (m0g + mt) * 16 + g;
            float* d = acc + (mt * 2 + nt) * 4;
            float c0 = -s.t[col] + __ldg(&b_ih[256 + col]) + __ldg(&b_hh[256 + col]);
            float c1 = -s.t[col + 1] + __ldg(&b_ih[256 + col + 1]) + __ldg(&b_hh[256 + col + 1]);
            float z0 = sigm(d[0] + c0);
            float z1 = sigm(d[1] + c1);
            float z2 = sigm(d[2] + c0);
            float z3 = sigm(d[3] + c1);
            float2 na = load_pair(s.a2h, s.a2l, r0, col);
            float2 nb = load_pair(s.a2h, s.a2l, r0 + 8, col);
            float2 ha = load_pair(s.a1h, s.a1l, r0, col);
            float2 hb = load_pair(s.a1h, s.a1l, r0 + 8, col);
            store_pair(s.a2h, s.a2l, r0, col,
                       (1.0f - z0) * na.x + z0 * ha.x,
                       (1.0f - z1) * na.y + z1 * ha.y);
            store_pair(s.a2h, s.a2l, r0 + 8, col,
                       (1.0f - z2) * nb.x + z2 * hb.x,
                       (1.0f - z3) * nb.y + z3 * hb.y);
        }
    }

    // ---- P6: v = h_new @ W_val^T + b_val -> a1 ----
    zero16(acc);
    gemm_pass<2, 2, false, 32>(s, s.a2h, s.a2l, g_whi + OFF_VAL, g_wlo + OFF_VAL,
                               0, 256, 256, 256, m0g, n0g, g, t4, tid, wid, acc);
    for (int mt = 0; mt < 2; ++mt) {
        for (int nt = 0; nt < 2; ++nt) {
            int col = n0g + nt * 8 + 2 * t4;
            int r0 = (m0g + mt) * 16 + g;
            const float* d = acc + (mt * 2 + nt) * 4;
            float b0 = __ldg(&b_val[col]);
            float b1 = __ldg(&b_val[col + 1]);
            store_pair(s.a1h, s.a1l, r0, col, d[0] + b0, d[1] + b1);
            store_pair(s.a1h, s.a1l, r0 + 8, col, d[2] + b0, d[3] + b1);
        }
    }

    // ---- P7: out = v @ W_dec^T + b_dec (64 cols; warps 0..15 in 2x8 grid) ----
    {
        float ad[8];
#pragma unroll
        for (int i = 0; i < 8; ++i) { ad[i] = 0.0f; }
        int mg7 = wid & 1;
        int ng7 = (wid >> 1) & 7;
        int m0d = mg7 * 2;
        int n0d = ng7 * 8;
        gemm_pass<1, 2, false, 16>(s, s.a1h, s.a1l, g_whi + OFF_DEC, g_wlo + OFF_DEC,
                                   0, 256, 256, 64, m0d, n0d, g, t4, tid, wid, ad);
        if (wid < 16) {
            float* out_b = out + (size_t)bid * ROWS * 64;
            int col = n0d + 2 * t4;
            float b0 = __ldg(&b_dec[col]);
            float b1 = __ldg(&b_dec[col + 1]);
            for (int mt = 0; mt < 2; ++mt) {
                int r0 = (m0d + mt) * 16 + g;
                const float* d = ad + mt * 4;
                float2 o0 = make_float2(d[0] + b0, d[1] + b1);
                float2 o1 = make_float2(d[2] + b0, d[3] + b1);
                *reinterpret_cast<float2*>(&out_b[r0 * 64 + col]) = o0;
                *reinterpret_cast<float2*>(&out_b[(r0 + 8) * 64 + col]) = o1;
            }
        }
    }
}

extern "C" void kernel_launch(void* const* d_in, const int* in_sizes, int n_in,
                              void* d_out, int out_size)
{
    const float* obs   = (const float*)d_in[0];
    const float* W_enc = (const float*)d_in[1];
    const float* b_enc = (const float*)d_in[2];
    const float* W_obs = (const float*)d_in[3];
    const float* b_obs = (const float*)d_in[4];
    const float* W_ih  = (const float*)d_in[5];
    const float* b_ih  = (const float*)d_in[6];
    const float* W_hh  = (const float*)d_in[7];
    const float* b_hh  = (const float*)d_in[8];
    const float* W_val = (const float*)d_in[9];
    const float* b_val = (const float*)d_in[10];
    const float* W_dec = (const float*)d_in[11];
    const float* b_dec = (const float*)d_in[12];
    float* out = (float*)d_out;
    (void)in_sizes; (void)n_in; (void)out_size;

    conv_weights<<<(W_TOTAL + 255) / 256, 256>>>(W_enc, W_obs, W_ih, W_hh, W_val, W_dec);

    cudaFuncSetAttribute(commnet_mma_kernel,
                         cudaFuncAttributeMaxDynamicSharedMemorySize, (int)sizeof(Smem));
    commnet_mma_kernel<<<256, NTHREADS, sizeof(Smem)>>>(
        obs, b_enc, b_obs, b_ih, b_hh, b_val, b_dec, out);
}

// round 13
// speedup vs baseline: 1.5280x; 1.5280x over previous
#include <cuda_runtime.h>
#include <cuda_fp16.h>
#include <stdint.h>
#include <math.h>

// CommNetWork fused, fp16 2-term split mma.sync (m16n8k16.f32.f16.f16.f32).
// B=256, N=64 agents, D_IN=128, H0=256, H1=256, H2=64. One CTA per batch.
// Precision: activations stored as single fp16 (2^-12); weights split
// w = wh + wl (both fp16): y = sum xh*wh + xh*wl  -> ~2.4e-4/layer error.
// This cuts MMA volume 3->2 terms vs the bf16x3 scheme (R12: HMMA-rate-bound
// at tensor=33% plateau) and removes the activation-lo array entirely.
// KCH=64 halves chunk count (38 vs 76) -> half the barrier/stage serialization.
// Comm factorization: c=(S-h)/64; W_ih pre-scaled by -1/64 so gi and gh share
// one accumulator; S-term t[col] accumulated from staged chunks.

#define ROWS    64
#define NTHREADS 512
#define LDA_ACT 264   // fp16 elems per activation row (256+8 pad)
#define LDW     72    // fp16 elems per weight-chunk row (64+8 pad)
#define KCH     64    // k per staged chunk (double buffered)

#define OFF_ENC 0
#define OFF_OBS 32768
#define OFF_IH  98304
#define OFF_HH  294912
#define OFF_VAL 491520
#define OFF_DEC 557056
#define W_TOTAL 573440

__device__ __align__(16) __half g_whi[W_TOTAL];
__device__ __align__(16) __half g_wlo[W_TOTAL];

struct Smem {
    __half a1[ROWS * LDA_ACT];     // 33792 B
    __half a2[ROWS * LDA_ACT];     // 33792 B
    __half wh[2][256 * LDW];       // 73728 B
    __half wl[2][256 * LDW];       // 73728 B
    float S[256];
    float t[256];
};  // 217088 bytes

// ------------------------- weight conversion pre-pass -------------------
__global__ void conv_weights(const float* __restrict__ enc, const float* __restrict__ obsw,
                             const float* __restrict__ ih,  const float* __restrict__ hh,
                             const float* __restrict__ val, const float* __restrict__ dec)
{
    int i = blockIdx.x * blockDim.x + threadIdx.x;
    if (i >= W_TOTAL) return;
    const float* src;
    int off;
    float scale = 1.0f;
    if (i < OFF_OBS)      { src = enc;  off = i; }
    else if (i < OFF_IH)  { src = obsw; off = i - OFF_OBS; }
    else if (i < OFF_HH)  { src = ih;   off = i - OFF_IH; scale = -0.015625f; }
    else if (i < OFF_VAL) { src = hh;   off = i - OFF_HH; }
    else if (i < OFF_DEC) { src = val;  off = i - OFF_VAL; }
    else                  { src = dec;  off = i - OFF_DEC; }
    float v = src[off] * scale;
    __half h = __float2half_rn(v);
    g_whi[i] = h;
    g_wlo[i] = __float2half_rn(v - __half2float(h));
}

// ------------------------- device helpers --------------------------------
__device__ __forceinline__ float sigm(float x) { return 1.0f / (1.0f + __expf(-x)); }

__device__ __forceinline__ void cp16(void* dst, const void* src) {
    uint32_t d = (uint32_t)__cvta_generic_to_shared(dst);
    asm volatile("cp.async.cg.shared.global [%0], [%1], 16;\n" :: "r"(d), "l"(src));
}
__device__ __forceinline__ void cp_commit() { asm volatile("cp.async.commit_group;\n" ::); }
__device__ __forceinline__ void cp_wait1()  { asm volatile("cp.async.wait_group 1;\n" ::); }
__device__ __forceinline__ void cp_wait0()  { asm volatile("cp.async.wait_group 0;\n" ::); }

__device__ __forceinline__ void mma_f16(float* d,
                                        uint32_t a0, uint32_t a1, uint32_t a2, uint32_t a3,
                                        uint32_t b0, uint32_t b1)
{
    asm volatile("mma.sync.aligned.m16n8k16.row.col.f32.f16.f16.f32 "
                 "{%0,%1,%2,%3}, {%4,%5,%6,%7}, {%8,%9}, {%0,%1,%2,%3};\n"
                 : "+f"(d[0]), "+f"(d[1]), "+f"(d[2]), "+f"(d[3])
                 : "r"(a0), "r"(a1), "r"(a2), "r"(a3), "r"(b0), "r"(b1));
}

// stage one [nrows x 64k] hi+lo weight chunk (row = 128B = 8x16B segs)
__device__ __forceinline__ void stage(Smem& s, int buf,
                                      const __half* __restrict__ ghi,
                                      const __half* __restrict__ glo,
                                      int col0, int Ksrc, int k0, int nrows, int tid)
{
    int total = nrows * 8;
    for (int idx = tid; idx < total; idx += NTHREADS) {
        int r = idx >> 3;
        int seg = idx & 7;
        size_t so = (size_t)(col0 + r) * Ksrc + k0 + seg * 8;
        cp16(&s.wh[buf][r * LDW + seg * 8], ghi + so);
        cp16(&s.wl[buf][r * LDW + seg * 8], glo + so);
    }
    cp_commit();
}

// one 64-k chunk: acc += A*Wh + A*Wl   (NT n8-tiles per warp, 4 m16-tiles)
template<int NT>
__device__ __forceinline__ void mma_chunk(const __half* __restrict__ ah,
                                          const __half* __restrict__ wh,
                                          const __half* __restrict__ wl,
                                          int kbase, int n0, int g, int t4, float* acc)
{
#pragma unroll
    for (int ks = 0; ks < 4; ++ks) {
        int klA = kbase + ks * 16 + 2 * t4;
        int klW = ks * 16 + 2 * t4;
        uint32_t bh0[NT], bh1[NT], bl0[NT], bl1[NT];
#pragma unroll
        for (int nt = 0; nt < NT; ++nt) {
            int wrow = (n0 + nt * 8 + g) * LDW + klW;
            bh0[nt] = *(const uint32_t*)&wh[wrow];
            bh1[nt] = *(const uint32_t*)&wh[wrow + 8];
            bl0[nt] = *(const uint32_t*)&wl[wrow];
            bl1[nt] = *(const uint32_t*)&wl[wrow + 8];
        }
#pragma unroll
        for (int mt = 0; mt < 4; ++mt) {
            int ab = (mt * 16 + g) * LDA_ACT + klA;
            uint32_t A0 = *(const uint32_t*)&ah[ab];
            uint32_t A1 = *(const uint32_t*)&ah[ab + 8 * LDA_ACT];
            uint32_t A2 = *(const uint32_t*)&ah[ab + 8];
            uint32_t A3 = *(const uint32_t*)&ah[ab + 8 * LDA_ACT + 8];
#pragma unroll
            for (int nt = 0; nt < NT; ++nt) {
                float* d = acc + (mt * NT + nt) * 4;
                mma_f16(d, A0, A1, A2, A3, bh0[nt], bh1[nt]);
                mma_f16(d, A0, A1, A2, A3, bl0[nt], bl1[nt]);
            }
        }
    }
}

// NACT: number of warps that run MMAs (all warps stage + sync).
template<int NT, bool TACC, int NACT>
__device__ __forceinline__ void gemm_pass(Smem& s,
                                          const __half* __restrict__ ah,
                                          const __half* __restrict__ ghi,
                                          const __half* __restrict__ glo,
                                          int col0, int Ksrc, int Kdim, int nrows,
                                          int n0, int g, int t4, int tid, int wid, float* acc)
{
    const int nch = Kdim / KCH;
    stage(s, 0, ghi, glo, col0, Ksrc, 0, nrows, tid);
    for (int c = 0; c < nch; ++c) {
        int cur = c & 1;
        bool more = (c + 1 < nch);
        if (more) {
            stage(s, 1 - cur, ghi, glo, col0, Ksrc, (c + 1) * KCH, nrows, tid);
            cp_wait1();
        } else {
            cp_wait0();
        }
        __syncthreads();
        if (TACC && tid < 256) {
            float sum = 0.0f;
            const __half* w1 = &s.wh[cur][tid * LDW];
            const __half* w2 = &s.wl[cur][tid * LDW];
#pragma unroll
            for (int kk = 0; kk < KCH; ++kk) {
                sum += s.S[c * KCH + kk] *
                       (__half2float(w1[kk]) + __half2float(w2[kk]));
            }
            s.t[tid] += sum;
        }
        if (wid < NACT) {
            mma_chunk<NT>(ah, s.wh[cur], s.wl[cur], c * KCH, n0, g, t4, acc);
        }
        __syncthreads();
    }
}

__device__ __forceinline__ void store_h2(__half* a, int row, int col, float v0, float v1)
{
    __half2 p;
    p.x = __float2half_rn(v0);
    p.y = __float2half_rn(v1);
    *reinterpret_cast<__half2*>(&a[row * LDA_ACT + col]) = p;
}

__device__ __forceinline__ float2 load_h2(const __half* a, int row, int col)
{
    __half2 p = *reinterpret_cast<const __half2*>(&a[row * LDA_ACT + col]);
    float2 r;
    r.x = __half2float(p.x);
    r.y = __half2float(p.y);
    return r;
}

__device__ __forceinline__ void zero32(float* a)
{
#pragma unroll
    for (int i = 0; i < 32; ++i) { a[i] = 0.0f; }
}

// ------------------------- main fused kernel -----------------------------
__global__ void __launch_bounds__(NTHREADS, 1)
commnet_mma_kernel(const float* __restrict__ obs,
                   const float* __restrict__ b_enc, const float* __restrict__ b_obs,
                   const float* __restrict__ b_ih,  const float* __restrict__ b_hh,
                   const float* __restrict__ b_val, const float* __restrict__ b_dec,
                   float* __restrict__ out)
{
    extern __shared__ char smem_raw[];
    Smem& s = *reinterpret_cast<Smem*>(smem_raw);

    const int tid  = threadIdx.x;
    const int bid  = blockIdx.x;
    const int wid  = tid >> 5;
    const int lane = tid & 31;
    const int g    = lane >> 2;
    const int t4   = lane & 3;
    const int n0g  = wid * 16;   // warp's 16-col base in 256-wide outputs

    float acc[32];

    // ---- P1: load obs [64 x 128] -> a1 fp16 ----
    {
        const float* ob = obs + (size_t)bid * ROWS * 128;
        for (int idx = tid; idx < ROWS * 128; idx += NTHREADS) {
            int r = idx >> 7;
            int k = idx & 127;
            s.a1[r * LDA_ACT + k] = __float2half_rn(ob[idx]);
        }
    }
    __syncthreads();

    // ---- P2: x = relu(obs @ W_enc^T + b_enc) -> a2 ----
    zero32(acc);
    gemm_pass<2, false, 16>(s, s.a1, g_whi + OFF_ENC, g_wlo + OFF_ENC,
                            0, 128, 128, 256, n0g, g, t4, tid, wid, acc);
    for (int mt = 0; mt < 4; ++mt) {
        for (int nt = 0; nt < 2; ++nt) {
            int col = n0g + nt * 8 + 2 * t4;
            int r0 = mt * 16 + g;
            const float* d = acc + (mt * 2 + nt) * 4;
            float b0 = __ldg(&b_enc[col]);
            float b1 = __ldg(&b_enc[col + 1]);
            store_h2(s.a2, r0, col, fmaxf(d[0] + b0, 0.0f), fmaxf(d[1] + b1, 0.0f));
            store_h2(s.a2, r0 + 8, col, fmaxf(d[2] + b0, 0.0f), fmaxf(d[3] + b1, 0.0f));
        }
    }

    // ---- P3: h = x @ W_obs^T + b_obs -> a1 ----
    zero32(acc);
    gemm_pass<2, false, 16>(s, s.a2, g_whi + OFF_OBS, g_wlo + OFF_OBS,
                            0, 256, 256, 256, n0g, g, t4, tid, wid, acc);
    for (int mt = 0; mt < 4; ++mt) {
        for (int nt = 0; nt < 2; ++nt) {
            int col = n0g + nt * 8 + 2 * t4;
            int r0 = mt * 16 + g;
            const float* d = acc + (mt * 2 + nt) * 4;
            float b0 = __ldg(&b_obs[col]);
            float b1 = __ldg(&b_obs[col + 1]);
            store_h2(s.a1, r0, col, d[0] + b0, d[1] + b1);
            store_h2(s.a1, r0 + 8, col, d[2] + b0, d[3] + b1);
        }
    }
    __syncthreads();

    // ---- P4: S = column sums of h ----
    if (tid < 256) {
        float sum = 0.0f;
#pragma unroll 8
        for (int r = 0; r < ROWS; ++r) {
            sum += __half2float(s.a1[r * LDA_ACT + tid]);
        }
        s.S[tid] = sum;
        s.t[tid] = 0.0f;
    }
    __syncthreads();

    // ======== P5 GRU (r, n, z; fragments round-trip through a2) ========

    // r gate
    zero32(acc);
    gemm_pass<2, false, 16>(s, s.a1, g_whi + OFF_HH, g_wlo + OFF_HH,
                            0, 256, 256, 256, n0g, g, t4, tid, wid, acc);
    gemm_pass<2, true, 16>(s, s.a1, g_whi + OFF_IH, g_wlo + OFF_IH,
                           0, 256, 256, 256, n0g, g, t4, tid, wid, acc);
    for (int mt = 0; mt < 4; ++mt) {
        for (int nt = 0; nt < 2; ++nt) {
            int col = n0g + nt * 8 + 2 * t4;
            int r0 = mt * 16 + g;
            float* d = acc + (mt * 2 + nt) * 4;
            float c0 = -s.t[col] + __ldg(&b_ih[col]) + __ldg(&b_hh[col]);
            float c1 = -s.t[col + 1] + __ldg(&b_ih[col + 1]) + __ldg(&b_hh[col + 1]);
            store_h2(s.a2, r0, col, sigm(d[0] + c0), sigm(d[1] + c1));
            store_h2(s.a2, r0 + 8, col, sigm(d[2] + c0), sigm(d[3] + c1));
        }
    }
    __syncthreads();
    if (tid < 256) { s.t[tid] = 0.0f; }

    // n gate
    zero32(acc);
    gemm_pass<2, false, 16>(s, s.a1, g_whi + OFF_HH, g_wlo + OFF_HH,
                            512, 256, 256, 256, n0g, g, t4, tid, wid, acc);
    for (int mt = 0; mt < 4; ++mt) {
        for (int nt = 0; nt < 2; ++nt) {
            int col = n0g + nt * 8 + 2 * t4;
            int r0 = mt * 16 + g;
            float* d = acc + (mt * 2 + nt) * 4;
            float b0 = __ldg(&b_hh[512 + col]);
            float b1 = __ldg(&b_hh[512 + col + 1]);
            float2 ra = load_h2(s.a2, r0, col);
            float2 rb = load_h2(s.a2, r0 + 8, col);
            d[0] = ra.x * (d[0] + b0);
            d[1] = ra.y * (d[1] + b1);
            d[2] = rb.x * (d[2] + b0);
            d[3] = rb.y * (d[3] + b1);
        }
    }
    gemm_pass<2, true, 16>(s, s.a1, g_whi + OFF_IH, g_wlo + OFF_IH,
                           512, 256, 256, 256, n0g, g, t4, tid, wid, acc);
    for (int mt = 0; mt < 4; ++mt) {
        for (int nt = 0; nt < 2; ++nt) {
            int col = n0g + nt * 8 + 2 * t4;
            int r0 = mt * 16 + g;
            float* d = acc + (mt * 2 + nt) * 4;
            float c0 = -s.t[col] + __ldg(&b_ih[512 + col]);
            float c1 = -s.t[col + 1] + __ldg(&b_ih[512 + col + 1]);
            store_h2(s.a2, r0, col, tanhf(d[0] + c0), tanhf(d[1] + c1));
            store_h2(s.a2, r0 + 8, col, tanhf(d[2] + c0), tanhf(d[3] + c1));
        }
    }
    __syncthreads();
    if (tid < 256) { s.t[tid] = 0.0f; }

    // z gate + blend: h_new = (1-z)*n + z*h_old -> a2
    zero32(acc);
    gemm_pass<2, false, 16>(s, s.a1, g_whi + OFF_HH, g_wlo + OFF_HH,
                            256, 256, 256, 256, n0g, g, t4, tid, wid, acc);
    gemm_pass<2, true, 16>(s, s.a1, g_whi + OFF_IH, g_wlo + OFF_IH,
                           256, 256, 256, 256, n0g, g, t4, tid, wid, acc);
    for (int mt = 0; mt < 4; ++mt) {
        for (int nt = 0; nt < 2; ++nt) {
            int col = n0g + nt * 8 + 2 * t4;
            int r0 = mt * 16 + g;
            float* d = acc + (mt * 2 + nt) * 4;
            float c0 = -s.t[col] + __ldg(&b_ih[256 + col]) + __ldg(&b_hh[256 + col]);
            float c1 = -s.t[col + 1] + __ldg(&b_ih[256 + col + 1]) + __ldg(&b_hh[256 + col + 1]);
            float z0 = sigm(d[0] + c0);
            float z1 = sigm(d[1] + c1);
            float z2 = sigm(d[2] + c0);
            float z3 = sigm(d[3] + c1);
            float2 na = load_h2(s.a2, r0, col);
            float2 nb = load_h2(s.a2, r0 + 8, col);
            float2 ha = load_h2(s.a1, r0, col);
            float2 hb = load_h2(s.a1, r0 + 8, col);
            store_h2(s.a2, r0, col,
                     (1.0f - z0) * na.x + z0 * ha.x,
                     (1.0f - z1) * na.y + z1 * ha.y);
            store_h2(s.a2, r0 + 8, col,
                     (1.0f - z2) * nb.x + z2 * hb.x,
                     (1.0f - z3) * nb.y + z3 * hb.y);
        }
    }

    // ---- P6: v = h_new @ W_val^T + b_val -> a1 ----
    zero32(acc);
    gemm_pass<2, false, 16>(s, s.a2, g_whi + OFF_VAL, g_wlo + OFF_VAL,
                            0, 256, 256, 256, n0g, g, t4, tid, wid, acc);
    for (int mt = 0; mt < 4; ++mt) {
        for (int nt = 0; nt < 2; ++nt) {
            int col = n0g + nt * 8 + 2 * t4;
            int r0 = mt * 16 + g;
            const float* d = acc + (mt * 2 + nt) * 4;
            float b0 = __ldg(&b_val[col]);
            float b1 = __ldg(&b_val[col + 1]);
            store_h2(s.a1, r0, col, d[0] + b0, d[1] + b1);
            store_h2(s.a1, r0 + 8, col, d[2] + b0, d[3] + b1);
        }
    }

    // ---- P7: out = v @ W_dec^T + b_dec (64 cols; warps 0..7 own 8 each) ----
    {
        float ad[16];
#pragma unroll
        for (int i = 0; i < 16; ++i) { ad[i] = 0.0f; }
        int n0d = (wid & 7) * 8;
        gemm_pass<1, false, 8>(s, s.a1, g_whi + OFF_DEC, g_wlo + OFF_DEC,
                               0, 256, 256, 64, n0d, g, t4, tid, wid, ad);
        if (wid < 8) {
            float* out_b = out + (size_t)bid * ROWS * 64;
            int col = n0d + 2 * t4;
            float b0 = __ldg(&b_dec[col]);
            float b1 = __ldg(&b_dec[col + 1]);
            for (int mt = 0; mt < 4; ++mt) {
                int r0 = mt * 16 + g;
                const float* d = ad + mt * 4;
                float2 o0 = make_float2(d[0] + b0, d[1] + b1);
                float2 o1 = make_float2(d[2] + b0, d[3] + b1);
                *reinterpret_cast<float2*>(&out_b[r0 * 64 + col]) = o0;
                *reinterpret_cast<float2*>(&out_b[(r0 + 8) * 64 + col]) = o1;
            }
        }
    }
}

extern "C" void kernel_launch(void* const* d_in, const int* in_sizes, int n_in,
                              void* d_out, int out_size)
{
    const float* obs   = (const float*)d_in[0];
    const float* W_enc = (const float*)d_in[1];
    const float* b_enc = (const float*)d_in[2];
    const float* W_obs = (const float*)d_in[3];
    const float* b_obs = (const float*)d_in[4];
    const float* W_ih  = (const float*)d_in[5];
    const float* b_ih  = (const float*)d_in[6];
    const float* W_hh  = (const float*)d_in[7];
    const float* b_hh  = (const float*)d_in[8];
    const float* W_val = (const float*)d_in[9];
    const float* b_val = (const float*)d_in[10];
    const float* W_dec = (const float*)d_in[11];
    const float* b_dec = (const float*)d_in[12];
    float* out = (float*)d_out;
    (void)in_sizes; (void)n_in; (void)out_size;

    conv_weights<<<(W_TOTAL + 255) / 256, 256>>>(W_enc, W_obs, W_ih, W_hh, W_val, W_dec);

    cudaFuncSetAttribute(commnet_mma_kernel,
                         cudaFuncAttributeMaxDynamicSharedMemorySize, (int)sizeof(Smem));
    commnet_mma_kernel<<<256, NTHREADS, sizeof(Smem)>>>(
        obs, b_enc, b_obs, b_ih, b_hh, b_val, b_dec, out);
}